// round 10
// baseline (speedup 1.0000x reference)
#include <cuda_runtime.h>
#include <cuda_bf16.h>
#include <cuda_fp16.h>
#include <cstdint>

#define BB   512          // batch
#define TM1  63           // T-1
#define NI   512          // input size N
#define HH   256          // hidden H
#define H4   1024         // 4*H
#define KTOT 768          // N + H (GEMM K)

#define OFF_IE 16515072UL                 // B*TM1*NI
#define OFF_W  24772608UL                 // OFF_IE + B*TM1*HH

// scratch (device globals: no allocations allowed)
__device__ __half g_t2h[BB * TM1 * NI];   // [b][s][n], fp16 (33 MB)
__device__ float g_t1p[BB * 16 * 64];     // t1 partials [b][hu_group][s] (2 MB)
__device__ float g_WcT[512 * 64];         // [k][s] transposed Wc, s padded to 64
__device__ float g_c[BB * HH];
// A = [wx | h], double-buffered by step parity (avoids cross-CTA h RAW race)
__device__ __nv_bfloat16 g_Ah[2][BB * KTOT];
__device__ __nv_bfloat16 g_Al[2][BB * KTOT];
__device__ __nv_bfloat16 g_Bh[H4 * KTOT]; // W = [W_ih | W_hh], hi
__device__ __nv_bfloat16 g_Bl[H4 * KTOT]; // lo

__device__ __forceinline__ float ftanh(float x) {
    float e = __expf(2.0f * x);
    return 1.0f - __fdividef(2.0f, e + 1.0f);
}
__device__ __forceinline__ float fsig(float x) {
    return __fdividef(1.0f, 1.0f + __expf(-x));
}
__device__ __forceinline__ float tanh_fast(float x) {
    float y; asm("tanh.approx.f32 %0, %1;" : "=f"(y) : "f"(x)); return y;
}
__device__ __forceinline__ uint32_t smem_u32(const void* p) {
    uint32_t a;
    asm("{ .reg .u64 t; cvta.to.shared.u64 t, %1; cvt.u32.u64 %0, t; }" : "=r"(a) : "l"(p));
    return a;
}

// ---------------------------------------------------------------- setup
__global__ void zero_kernel() {
    int i = blockIdx.x * 256 + threadIdx.x;
    if (i < BB * HH) g_c[i] = 0.0f;
    if (i < BB * 16 * 64) g_t1p[i] = 0.0f;
    if (i < 2 * BB * KTOT) {
        (&g_Ah[0][0])[i] = __float2bfloat16(0.0f);
        (&g_Al[0][0])[i] = __float2bfloat16(0.0f);
    }
}

__global__ void convw_kernel(const float* __restrict__ Wih,
                             const float* __restrict__ Whh) {
    int i = blockIdx.x * 256 + threadIdx.x;
    if (i >= H4 * KTOT) return;
    int g = i / KTOT, k = i - g * KTOT;
    float w = (k < NI) ? Wih[g * NI + k] : Whh[g * HH + (k - NI)];
    __nv_bfloat16 hi = __float2bfloat16(w);
    g_Bh[i] = hi;
    g_Bl[i] = __float2bfloat16(w - __bfloat162float(hi));
}

__global__ void transWc_kernel(const float* __restrict__ Wc) {
    int i = blockIdx.x * 256 + threadIdx.x;   // 512*64
    if (i >= 512 * 64) return;
    int k = i >> 6, s = i & 63;
    g_WcT[i] = (s < TM1) ? Wc[s * 512 + k] : 0.0f;
}

// t2[b][s][n] = sum_t x[b][t][n] * Wd[s][t] + bd[s]  -> fp16, paired stores
__global__ void t2_kernel(const float* __restrict__ x,
                          const float* __restrict__ Wd,
                          const float* __restrict__ bd) {
    __shared__ __align__(16) float wdT[TM1 * 64];
    int tid = threadIdx.x;
    for (int idx = tid; idx < TM1 * 64; idx += 128) {
        int t = idx >> 6, s = idx & 63;
        wdT[idx] = (s < TM1) ? Wd[s * TM1 + t] : 0.0f;
    }
    __syncthreads();

    int b = blockIdx.x;
    int n = blockIdx.y * 128 + tid;
    int s0 = blockIdx.z * 32;
    float acc[32];
#pragma unroll
    for (int s = 0; s < 32; s++) acc[s] = 0.0f;

    const float* xp = x + (size_t)(b * TM1) * NI + n;
    for (int t = 0; t < TM1; t++) {
        float xv = xp[(size_t)t * NI];
        const float4* wrow = reinterpret_cast<const float4*>(&wdT[t * 64 + s0]);
#pragma unroll
        for (int q = 0; q < 8; q++) {
            float4 w = wrow[q];
            acc[q * 4 + 0] += xv * w.x;
            acc[q * 4 + 1] += xv * w.y;
            acc[q * 4 + 2] += xv * w.z;
            acc[q * 4 + 3] += xv * w.w;
        }
    }
    __half* t2p = g_t2h + (size_t)(b * TM1) * NI + n;
#pragma unroll
    for (int s = 0; s < 32; s++) {
        int sg = s0 + s;
        if (sg < TM1) {
            float v = acc[s] + bd[sg];
            float o = __shfl_xor_sync(0xffffffffu, v, 1);
            if (!(tid & 1))
                *reinterpret_cast<__half2*>(t2p + (size_t)sg * NI) =
                    __floats2half2_rn(v, o);
        }
    }
}

// ---------------------------------------------------------------- per-step
// attention: t1 = bc + sum of 16 partials; scores -> softmax -> wx.
__global__ void __launch_bounds__(256) attn_kernel(const float* __restrict__ x,
                                                   const float* __restrict__ Wa,
                                                   const float* __restrict__ ba,
                                                   const float* __restrict__ bc,
                                                   float* __restrict__ out, int t) {
    __shared__ float t1s[64];
    __shared__ float was[64];
    __shared__ float part[256];
    __shared__ float red[16];
    int tid = threadIdx.x, b = blockIdx.x;
    int lane = tid & 31, wid = tid >> 5;

    const float* p = g_t1p + (size_t)b * 1024;
    part[tid] = p[tid] + p[256 + tid] + p[512 + tid] + p[768 + tid];
    if (tid < 64) was[tid] = (tid < TM1) ? Wa[tid] : 0.0f;
    __syncthreads();
    if (tid < 64)
        t1s[tid] = ((tid < TM1) ? bc[tid] : 0.0f) +
                   part[tid] + part[64 + tid] + part[128 + tid] + part[192 + tid];
    __syncthreads();

    float bav = ba[0];
    float sc0 = bav, sc1 = bav;
    const __half2* t2p =
        reinterpret_cast<const __half2*>(g_t2h + (size_t)(b * TM1) * NI) + tid;
#pragma unroll 7
    for (int s = 0; s < TM1; s++) {
        float2 v = __half22float2(t2p[(size_t)s * (NI / 2)]);
        float ws = was[s], t1v = t1s[s];
        sc0 += ws * tanh_fast(t1v + v.x);
        sc1 += ws * tanh_fast(t1v + v.y);
    }

    float v = fmaxf(sc0, sc1);
#pragma unroll
    for (int o = 16; o; o >>= 1) v = fmaxf(v, __shfl_xor_sync(0xffffffffu, v, o));
    if (lane == 0) red[wid] = v;
    __syncthreads();
    if (tid < 32) {
        float m = (tid < 8) ? red[tid] : -3.4e38f;
#pragma unroll
        for (int o = 4; o; o >>= 1) m = fmaxf(m, __shfl_xor_sync(0xffffffffu, m, o));
        if (tid == 0) red[8] = m;
    }
    __syncthreads();
    float m = red[8];
    float e0 = __expf(sc0 - m), e1 = __expf(sc1 - m);
    v = e0 + e1;
#pragma unroll
    for (int o = 16; o; o >>= 1) v += __shfl_xor_sync(0xffffffffu, v, o);
    if (lane == 0) red[wid] = v;
    __syncthreads();
    if (tid < 32) {
        float s2 = (tid < 8) ? red[tid] : 0.0f;
#pragma unroll
        for (int o = 4; o; o >>= 1) s2 += __shfl_xor_sync(0xffffffffu, s2, o);
        if (tid == 0) red[9] = s2;
    }
    __syncthreads();
    float inv = __fdividef(1.0f, red[9]);
    float a0 = e0 * inv, a1 = e1 * inv;

    float2 xv = reinterpret_cast<const float2*>(x + (size_t)(b * TM1 + t) * NI)[tid];
    float wx0 = a0 * xv.x, wx1 = a1 * xv.y;
    reinterpret_cast<float2*>(out + (size_t)(b * TM1 + t) * NI)[tid] =
        make_float2(wx0, wx1);
    reinterpret_cast<float2*>(out + OFF_W + (size_t)(b * TM1 + t) * NI)[tid] =
        make_float2(a0, a1);

    int par = t & 1;
    __nv_bfloat162 hi2 = __floats2bfloat162_rn(wx0, wx1);
    reinterpret_cast<__nv_bfloat162*>(g_Ah[par] + (size_t)b * KTOT)[tid] = hi2;
    float l0 = wx0 - __bfloat162float(hi2.x);
    float l1 = wx1 - __bfloat162float(hi2.y);
    reinterpret_cast<__nv_bfloat162*>(g_Al[par] + (size_t)b * KTOT)[tid] =
        __floats2bfloat162_rn(l0, l1);
}

// ---------------------------------------------------------------- HMMA cell
// 128 CTAs: 8 M-tiles (64 batch) x 16 hu-tiles. 4 warps, warp tile 16x64,
// gate-major N packing, fused LSTM epilogue + fused t1-partial computation.
// 3-stage cp.async ring.
#define LDA 144           // padded A/B row stride in bytes (72 bf16)
#define TA_H 0
#define TA_L 9216
#define TB_H 18432
#define TB_L 27648
#define TILE_BYTES 36864
#define SM_WCT 256                       // 32 x 65 floats = 8320 B
#define SM_TILES 8576
#define CELL_SMEM (SM_TILES + 3 * TILE_BYTES)

__device__ __forceinline__ void cp16(uint32_t dst, const void* src) {
    asm volatile("cp.async.cg.shared.global [%0], [%1], 16;" :: "r"(dst), "l"(src) : "memory");
}
#define LDSM4(r, addr)                                                         \
    asm volatile("ldmatrix.sync.aligned.m8n8.x4.shared.b16 {%0,%1,%2,%3}, [%4];" \
        : "=r"((r)[0]), "=r"((r)[1]), "=r"((r)[2]), "=r"((r)[3]) : "r"(addr))
#define MMA16816(d, a, b)                                                      \
    asm volatile("mma.sync.aligned.m16n8k16.row.col.f32.bf16.bf16.f32 "        \
        "{%0,%1,%2,%3},{%4,%5,%6,%7},{%8,%9},{%0,%1,%2,%3};"                   \
        : "+f"((d)[0]), "+f"((d)[1]), "+f"((d)[2]), "+f"((d)[3])               \
        : "r"((a)[0]), "r"((a)[1]), "r"((a)[2]), "r"((a)[3]),                  \
          "r"((b)[0]), "r"((b)[1]))

__device__ __forceinline__ void load_tile(int par, uint32_t sbuf, int kt,
                                          int b0, int hu0, int tid) {
    int k0 = kt * 64;
    const __nv_bfloat16* Ah = g_Ah[par];
    const __nv_bfloat16* Al = g_Al[par];
#pragma unroll
    for (int j = 0; j < 4; j++) {
        int id = tid + 128 * j;               // 512 = 64 rows x 8 chunks
        int row = id >> 3, c16 = id & 7;
        uint32_t off = row * LDA + c16 * 16;
        size_t src = (size_t)(b0 + row) * KTOT + k0 + c16 * 8;
        cp16(sbuf + TA_H + off, Ah + src);
        cp16(sbuf + TA_L + off, Al + src);
    }
#pragma unroll
    for (int j = 0; j < 4; j++) {
        int id = tid + 128 * j;               // 512 = 64 rows x 8 chunks
        int row = id >> 3, c16 = id & 7;
        int grow = (row >> 4) * HH + hu0 + (row & 15);  // gate-major packing
        uint32_t off = row * LDA + c16 * 16;
        size_t src = (size_t)grow * KTOT + k0 + c16 * 8;
        cp16(sbuf + TB_H + off, g_Bh + src);
        cp16(sbuf + TB_L + off, g_Bl + src);
    }
}

__global__ void __launch_bounds__(128, 1)
cell_kernel(const float* __restrict__ bih, const float* __restrict__ bhh,
            float* __restrict__ out, int t) {
    extern __shared__ char smem[];
    uint32_t sb = smem_u32(smem);
    int tid = threadIdx.x, w = tid >> 5, lane = tid & 31;
    int b0 = (blockIdx.x & 7) * 64;
    int ghu = blockIdx.x >> 3;
    int hu0 = ghu * 16;
    int par = t & 1;

    float* bsum = (float*)smem;
    float* swct = (float*)(smem + SM_WCT);

    if (tid < 64) {
        int grow = (tid >> 4) * HH + hu0 + (tid & 15);
        bsum[tid] = bih[grow] + bhh[grow];
    }

    float acc[8][4];
#pragma unroll
    for (int j = 0; j < 8; j++)
#pragma unroll
        for (int k = 0; k < 4; k++) acc[j][k] = 0.0f;

    // 3-stage prologue
    load_tile(par, sb + SM_TILES, 0, b0, hu0, tid);
    asm volatile("cp.async.commit_group;" ::: "memory");
    load_tile(par, sb + SM_TILES + TILE_BYTES, 1, b0, hu0, tid);
    asm volatile("cp.async.commit_group;" ::: "memory");

    // Wc rows for this CTA's units (h rows 0-15, c rows 16-31), padded 65
    for (int i = tid; i < 32 * 64; i += 128) {
        int r = i >> 6, s = i & 63;
        int k = (r < 16) ? (hu0 + r) : (256 + hu0 + (r - 16));
        swct[r * 65 + s] = g_WcT[k * 64 + s];
    }

    for (int kt = 0; kt < 12; kt++) {
        if (kt < 10) {
            load_tile(par, sb + SM_TILES + ((kt + 2) % 3) * TILE_BYTES,
                      kt + 2, b0, hu0, tid);
            asm volatile("cp.async.commit_group;" ::: "memory");
            asm volatile("cp.async.wait_group 2;" ::: "memory");
        } else if (kt == 10) {
            asm volatile("cp.async.wait_group 1;" ::: "memory");
        } else {
            asm volatile("cp.async.wait_group 0;" ::: "memory");
        }
        __syncthreads();
        uint32_t base = sb + SM_TILES + (kt % 3) * TILE_BYTES;

#pragma unroll
        for (int ks = 0; ks < 4; ks++) {
            int k0 = ks * 16;
            uint32_t aH[4], aL[4];
            uint32_t bH[16], bL[16];
            uint32_t ar = base + TA_H +
                (w * 16 + (lane & 15)) * LDA + (k0 + (lane >> 4) * 8) * 2;
            LDSM4(aH, ar);
            LDSM4(aL, ar + (TA_L - TA_H));
            int g4 = lane >> 3;
#pragma unroll
            for (int p = 0; p < 4; p++) {
                uint32_t br = base + TB_H +
                    (p * 16 + (g4 >> 1) * 8 + (lane & 7)) * LDA +
                    (k0 + (g4 & 1) * 8) * 2;
                LDSM4(bH + p * 4, br);
                LDSM4(bL + p * 4, br + (TB_L - TB_H));
            }
#pragma unroll
            for (int st = 0; st < 8; st++) MMA16816(acc[st], aH, bH + st * 2);
#pragma unroll
            for (int st = 0; st < 8; st++) MMA16816(acc[st], aH, bL + st * 2);
#pragma unroll
            for (int st = 0; st < 8; st++) MMA16816(acc[st], aL, bH + st * 2);
        }
        __syncthreads();
    }

    // phase 1: LSTM epilogue; stash h,c in smem (reuses tile area) for t1 partials
    float* hcs = (float*)(smem + SM_TILES);   // [64][32]: u<16 = h, u+16 = c
    int qr = lane >> 2, qc = (lane & 3) * 2;
    int wpar = (t + 1) & 1;
    __nv_bfloat16* Ahn = g_Ah[wpar];
    __nv_bfloat16* Aln = g_Al[wpar];
#pragma unroll
    for (int rr = 0; rr < 2; rr++) {
        int bl = w * 16 + rr * 8 + qr;
        int b = b0 + bl;
#pragma unroll
        for (int ug = 0; ug < 2; ug++) {
#pragma unroll
            for (int cc = 0; cc < 2; cc++) {
                int u = ug * 8 + qc + cc;
                int ri = rr * 2 + cc;
                float gi = acc[ug][ri]     + bsum[u];
                float gf = acc[2 + ug][ri] + bsum[16 + u];
                float gg = acc[4 + ug][ri] + bsum[32 + u];
                float go = acc[6 + ug][ri] + bsum[48 + u];
                float I = fsig(gi), F = fsig(gf), G = ftanh(gg), O = fsig(go);
                int hu = hu0 + u;
                int idx = b * HH + hu;
                float c = F * g_c[idx] + I * G;
                float h = O * ftanh(c);
                g_c[idx] = c;
                hcs[bl * 32 + u] = h;
                hcs[bl * 32 + 16 + u] = c;
                out[OFF_IE + (size_t)(b * TM1 + t) * HH + hu] = h;
                __nv_bfloat16 hb = __float2bfloat16(h);
                Ahn[(size_t)b * KTOT + NI + hu] = hb;
                Aln[(size_t)b * KTOT + NI + hu] =
                    __float2bfloat16(h - __bfloat162float(hb));
            }
        }
    }
    __syncthreads();

    // phase 2: t1 partial for step t+1: p[b][ghu][s] = sum_u h*Wc_h + c*Wc_c
    if (tid < 126) {
        int s = tid >> 1, bh = tid & 1;
        float wv[32];
#pragma unroll
        for (int k = 0; k < 32; k++) wv[k] = swct[k * 65 + s];
#pragma unroll 4
        for (int i = 0; i < 32; i++) {
            int bl = bh * 32 + i;
            const float4* hp = reinterpret_cast<const float4*>(hcs + bl * 32);
            float v = 0.0f;
#pragma unroll
            for (int j = 0; j < 8; j++) {
                float4 q = hp[j];
                v += q.x * wv[4 * j] + q.y * wv[4 * j + 1] +
                     q.z * wv[4 * j + 2] + q.w * wv[4 * j + 3];
            }
            g_t1p[(size_t)(b0 + bl) * 1024 + ghu * 64 + s] = v;
        }
    }
}

// ---------------------------------------------------------------- launch
extern "C" void kernel_launch(void* const* d_in, const int* in_sizes, int n_in,
                              void* d_out, int out_size) {
    const float* x   = (const float*)d_in[0];
    const float* Wih = (const float*)d_in[1];
    const float* Whh = (const float*)d_in[2];
    const float* bih = (const float*)d_in[3];
    const float* bhh = (const float*)d_in[4];
    const float* Wc  = (const float*)d_in[5];
    const float* bc  = (const float*)d_in[6];
    const float* Wd  = (const float*)d_in[7];
    const float* bd  = (const float*)d_in[8];
    const float* Wa  = (const float*)d_in[9];
    const float* ba  = (const float*)d_in[10];
    float* out = (float*)d_out;

    cudaFuncSetAttribute(cell_kernel, cudaFuncAttributeMaxDynamicSharedMemorySize, CELL_SMEM);

    zero_kernel<<<(2 * BB * KTOT + 255) / 256, 256>>>();
    convw_kernel<<<(H4 * KTOT + 255) / 256, 256>>>(Wih, Whh);
    transWc_kernel<<<(512 * 64 + 255) / 256, 256>>>(Wc);
    t2_kernel<<<dim3(BB, 4, 2), 128>>>(x, Wd, bd);

    for (int t = 0; t < TM1; t++) {
        attn_kernel<<<512, 256>>>(x, Wa, ba, bc, out, t);
        cell_kernel<<<128, 128, CELL_SMEM>>>(bih, bhh, out, t);
    }
}

// round 11
// speedup vs baseline: 1.1904x; 1.1904x over previous
#include <cuda_runtime.h>
#include <cuda_bf16.h>
#include <cuda_fp16.h>
#include <cstdint>

#define BB   512          // batch
#define TM1  63           // T-1
#define NI   512          // input size N
#define HH   256          // hidden H
#define H4   1024         // 4*H
#define KTOT 768          // N + H (GEMM K)

#define OFF_IE 16515072UL                 // B*TM1*NI
#define OFF_W  24772608UL                 // OFF_IE + B*TM1*HH

// scratch (device globals: no allocations allowed)
__device__ __half g_t2h[BB * TM1 * NI];   // [b][s][n], fp16 (33 MB)
__device__ float g_t1p[BB * 16 * 64];     // t1 partials [b][hu_group][s] (2 MB)
__device__ float g_WcT[512 * 64];         // [k][s] transposed Wc, s padded to 64
__device__ float g_c[BB * HH];
// A = [wx | h], double-buffered by step parity (avoids cross-CTA h RAW race)
__device__ __nv_bfloat16 g_Ah[2][BB * KTOT];
__device__ __nv_bfloat16 g_Al[2][BB * KTOT];
__device__ __nv_bfloat16 g_Bh[H4 * KTOT]; // W = [W_ih | W_hh], hi
__device__ __nv_bfloat16 g_Bl[H4 * KTOT]; // lo

__device__ __forceinline__ float ftanh(float x) {
    float e = __expf(2.0f * x);
    return 1.0f - __fdividef(2.0f, e + 1.0f);
}
__device__ __forceinline__ float fsig(float x) {
    return __fdividef(1.0f, 1.0f + __expf(-x));
}
__device__ __forceinline__ float tanh_fast(float x) {
    float y; asm("tanh.approx.f32 %0, %1;" : "=f"(y) : "f"(x)); return y;
}
__device__ __forceinline__ uint32_t smem_u32(const void* p) {
    uint32_t a;
    asm("{ .reg .u64 t; cvta.to.shared.u64 t, %1; cvt.u32.u64 %0, t; }" : "=r"(a) : "l"(p));
    return a;
}
__device__ __forceinline__ void pdl_trigger() {
    asm volatile("griddepcontrol.launch_dependents;" ::: "memory");
}
__device__ __forceinline__ void pdl_wait() {
    asm volatile("griddepcontrol.wait;" ::: "memory");
}

// ---------------------------------------------------------------- setup
__global__ void zero_kernel() {
    int i = blockIdx.x * 256 + threadIdx.x;
    if (i < BB * HH) g_c[i] = 0.0f;
    if (i < BB * 16 * 64) g_t1p[i] = 0.0f;
    if (i < 2 * BB * KTOT) {
        (&g_Ah[0][0])[i] = __float2bfloat16(0.0f);
        (&g_Al[0][0])[i] = __float2bfloat16(0.0f);
    }
}

__global__ void convw_kernel(const float* __restrict__ Wih,
                             const float* __restrict__ Whh) {
    int i = blockIdx.x * 256 + threadIdx.x;
    if (i >= H4 * KTOT) return;
    int g = i / KTOT, k = i - g * KTOT;
    float w = (k < NI) ? Wih[g * NI + k] : Whh[g * HH + (k - NI)];
    __nv_bfloat16 hi = __float2bfloat16(w);
    g_Bh[i] = hi;
    g_Bl[i] = __float2bfloat16(w - __bfloat162float(hi));
}

__global__ void transWc_kernel(const float* __restrict__ Wc) {
    int i = blockIdx.x * 256 + threadIdx.x;   // 512*64
    if (i >= 512 * 64) return;
    int k = i >> 6, s = i & 63;
    g_WcT[i] = (s < TM1) ? Wc[s * 512 + k] : 0.0f;
}

// t2[b][s][n] = sum_t x[b][t][n] * Wd[s][t] + bd[s]  -> fp16, paired stores
__global__ void t2_kernel(const float* __restrict__ x,
                          const float* __restrict__ Wd,
                          const float* __restrict__ bd) {
    __shared__ __align__(16) float wdT[TM1 * 64];
    int tid = threadIdx.x;
    for (int idx = tid; idx < TM1 * 64; idx += 128) {
        int t = idx >> 6, s = idx & 63;
        wdT[idx] = (s < TM1) ? Wd[s * TM1 + t] : 0.0f;
    }
    __syncthreads();

    int b = blockIdx.x;
    int n = blockIdx.y * 128 + tid;
    int s0 = blockIdx.z * 32;
    float acc[32];
#pragma unroll
    for (int s = 0; s < 32; s++) acc[s] = 0.0f;

    const float* xp = x + (size_t)(b * TM1) * NI + n;
    for (int t = 0; t < TM1; t++) {
        float xv = xp[(size_t)t * NI];
        const float4* wrow = reinterpret_cast<const float4*>(&wdT[t * 64 + s0]);
#pragma unroll
        for (int q = 0; q < 8; q++) {
            float4 w = wrow[q];
            acc[q * 4 + 0] += xv * w.x;
            acc[q * 4 + 1] += xv * w.y;
            acc[q * 4 + 2] += xv * w.z;
            acc[q * 4 + 3] += xv * w.w;
        }
    }
    __half* t2p = g_t2h + (size_t)(b * TM1) * NI + n;
#pragma unroll
    for (int s = 0; s < 32; s++) {
        int sg = s0 + s;
        if (sg < TM1) {
            float v = acc[s] + bd[sg];
            float o = __shfl_xor_sync(0xffffffffu, v, 1);
            if (!(tid & 1))
                *reinterpret_cast<__half2*>(t2p + (size_t)sg * NI) =
                    __floats2half2_rn(v, o);
        }
    }
}

// ---------------------------------------------------------------- per-step
// attention with PDL: prefetch t2/x pre-sync (step-invariant), t1p post-sync.
__global__ void __launch_bounds__(256) attn_kernel(const float* __restrict__ x,
                                                   const float* __restrict__ Wa,
                                                   const float* __restrict__ ba,
                                                   const float* __restrict__ bc,
                                                   float* __restrict__ out, int t) {
    __shared__ float t1s[64];
    __shared__ float was[64];
    __shared__ float part[256];
    __shared__ float red[16];
    int tid = threadIdx.x, b = blockIdx.x;
    int lane = tid & 31, wid = tid >> 5;

    pdl_trigger();   // successors' pre-sync phase touches only step-invariant data

    // -------- pre-sync: prefetch t2 slice + x (written only at setup / input)
    uint32_t pf[TM1];
    const uint32_t* t2p =
        reinterpret_cast<const uint32_t*>(g_t2h + (size_t)(b * TM1) * NI) + tid;
#pragma unroll
    for (int s = 0; s < TM1; s++) pf[s] = t2p[(size_t)s * (NI / 2)];
    float2 xv = reinterpret_cast<const float2*>(x + (size_t)(b * TM1 + t) * NI)[tid];
    if (tid < 64) was[tid] = (tid < TM1) ? Wa[tid] : 0.0f;
    float bav = ba[0];

    pdl_wait();      // cell(t-1) fully done -> t1p valid

    const float* p = g_t1p + (size_t)b * 1024;
    part[tid] = p[tid] + p[256 + tid] + p[512 + tid] + p[768 + tid];
    __syncthreads();
    if (tid < 64)
        t1s[tid] = ((tid < TM1) ? bc[tid] : 0.0f) +
                   part[tid] + part[64 + tid] + part[128 + tid] + part[192 + tid];
    __syncthreads();

    float sc0 = bav, sc1 = bav;
#pragma unroll
    for (int s = 0; s < TM1; s++) {
        __half2 h2 = *reinterpret_cast<__half2*>(&pf[s]);
        float2 v = __half22float2(h2);
        float ws = was[s], t1v = t1s[s];
        sc0 += ws * tanh_fast(t1v + v.x);
        sc1 += ws * tanh_fast(t1v + v.y);
    }

    float v = fmaxf(sc0, sc1);
#pragma unroll
    for (int o = 16; o; o >>= 1) v = fmaxf(v, __shfl_xor_sync(0xffffffffu, v, o));
    if (lane == 0) red[wid] = v;
    __syncthreads();
    if (tid < 32) {
        float m = (tid < 8) ? red[tid] : -3.4e38f;
#pragma unroll
        for (int o = 4; o; o >>= 1) m = fmaxf(m, __shfl_xor_sync(0xffffffffu, m, o));
        if (tid == 0) red[8] = m;
    }
    __syncthreads();
    float m = red[8];
    float e0 = __expf(sc0 - m), e1 = __expf(sc1 - m);
    v = e0 + e1;
#pragma unroll
    for (int o = 16; o; o >>= 1) v += __shfl_xor_sync(0xffffffffu, v, o);
    if (lane == 0) red[wid] = v;
    __syncthreads();
    if (tid < 32) {
        float s2 = (tid < 8) ? red[tid] : 0.0f;
#pragma unroll
        for (int o = 4; o; o >>= 1) s2 += __shfl_xor_sync(0xffffffffu, s2, o);
        if (tid == 0) red[9] = s2;
    }
    __syncthreads();
    float inv = __fdividef(1.0f, red[9]);
    float a0 = e0 * inv, a1 = e1 * inv;

    float wx0 = a0 * xv.x, wx1 = a1 * xv.y;
    reinterpret_cast<float2*>(out + (size_t)(b * TM1 + t) * NI)[tid] =
        make_float2(wx0, wx1);
    reinterpret_cast<float2*>(out + OFF_W + (size_t)(b * TM1 + t) * NI)[tid] =
        make_float2(a0, a1);

    int par = t & 1;
    __nv_bfloat162 hi2 = __floats2bfloat162_rn(wx0, wx1);
    reinterpret_cast<__nv_bfloat162*>(g_Ah[par] + (size_t)b * KTOT)[tid] = hi2;
    float l0 = wx0 - __bfloat162float(hi2.x);
    float l1 = wx1 - __bfloat162float(hi2.y);
    reinterpret_cast<__nv_bfloat162*>(g_Al[par] + (size_t)b * KTOT)[tid] =
        __floats2bfloat162_rn(l0, l1);
}

// ---------------------------------------------------------------- HMMA cell
// 128 CTAs: 8 M-tiles (64 batch) x 16 hu-tiles. 4 warps, warp tile 16x64,
// gate-major N packing, fused LSTM epilogue + fused t1-partials, 3-stage ring.
// PDL: B (weight) tiles + Wc + biases load pre-sync; A tiles post-sync.
#define LDA 144           // padded A/B row stride in bytes (72 bf16)
#define TA_H 0
#define TA_L 9216
#define TB_H 18432
#define TB_L 27648
#define TILE_BYTES 36864
#define SM_WCT 256                       // 32 x 65 floats = 8320 B
#define SM_TILES 8576
#define CELL_SMEM (SM_TILES + 3 * TILE_BYTES)

__device__ __forceinline__ void cp16(uint32_t dst, const void* src) {
    asm volatile("cp.async.cg.shared.global [%0], [%1], 16;" :: "r"(dst), "l"(src) : "memory");
}
#define LDSM4(r, addr)                                                         \
    asm volatile("ldmatrix.sync.aligned.m8n8.x4.shared.b16 {%0,%1,%2,%3}, [%4];" \
        : "=r"((r)[0]), "=r"((r)[1]), "=r"((r)[2]), "=r"((r)[3]) : "r"(addr))
#define MMA16816(d, a, b)                                                      \
    asm volatile("mma.sync.aligned.m16n8k16.row.col.f32.bf16.bf16.f32 "        \
        "{%0,%1,%2,%3},{%4,%5,%6,%7},{%8,%9},{%0,%1,%2,%3};"                   \
        : "+f"((d)[0]), "+f"((d)[1]), "+f"((d)[2]), "+f"((d)[3])               \
        : "r"((a)[0]), "r"((a)[1]), "r"((a)[2]), "r"((a)[3]),                  \
          "r"((b)[0]), "r"((b)[1]))

__device__ __forceinline__ void load_tileA(int par, uint32_t sbuf, int kt,
                                           int b0, int tid) {
    int k0 = kt * 64;
    const __nv_bfloat16* Ah = g_Ah[par];
    const __nv_bfloat16* Al = g_Al[par];
#pragma unroll
    for (int j = 0; j < 4; j++) {
        int id = tid + 128 * j;               // 512 = 64 rows x 8 chunks
        int row = id >> 3, c16 = id & 7;
        uint32_t off = row * LDA + c16 * 16;
        size_t src = (size_t)(b0 + row) * KTOT + k0 + c16 * 8;
        cp16(sbuf + TA_H + off, Ah + src);
        cp16(sbuf + TA_L + off, Al + src);
    }
}
__device__ __forceinline__ void load_tileB(uint32_t sbuf, int kt,
                                           int hu0, int tid) {
    int k0 = kt * 64;
#pragma unroll
    for (int j = 0; j < 4; j++) {
        int id = tid + 128 * j;               // 512 = 64 rows x 8 chunks
        int row = id >> 3, c16 = id & 7;
        int grow = (row >> 4) * HH + hu0 + (row & 15);  // gate-major packing
        uint32_t off = row * LDA + c16 * 16;
        size_t src = (size_t)grow * KTOT + k0 + c16 * 8;
        cp16(sbuf + TB_H + off, g_Bh + src);
        cp16(sbuf + TB_L + off, g_Bl + src);
    }
}

__global__ void __launch_bounds__(128, 1)
cell_kernel(const float* __restrict__ bih, const float* __restrict__ bhh,
            float* __restrict__ out, int t) {
    extern __shared__ char smem[];
    uint32_t sb = smem_u32(smem);
    int tid = threadIdx.x, w = tid >> 5, lane = tid & 31;
    int b0 = (blockIdx.x & 7) * 64;
    int ghu = blockIdx.x >> 3;
    int hu0 = ghu * 16;
    int par = t & 1;

    float* bsum = (float*)smem;
    float* swct = (float*)(smem + SM_WCT);

    pdl_trigger();   // attn(t+1)'s pre-sync reads only t2h/x/Wa

    // -------- pre-sync: weights, biases, Wc (all step-invariant)
    load_tileB(sb + SM_TILES, 0, hu0, tid);                 // G0
    asm volatile("cp.async.commit_group;" ::: "memory");
    load_tileB(sb + SM_TILES + TILE_BYTES, 1, hu0, tid);    // G1
    asm volatile("cp.async.commit_group;" ::: "memory");

    if (tid < 64) {
        int grow = (tid >> 4) * HH + hu0 + (tid & 15);
        bsum[tid] = bih[grow] + bhh[grow];
    }
    for (int i = tid; i < 32 * 64; i += 128) {
        int r = i >> 6, s = i & 63;
        int k = (r < 16) ? (hu0 + r) : (256 + hu0 + (r - 16));
        swct[r * 65 + s] = g_WcT[k * 64 + s];
    }

    float acc[8][4];
#pragma unroll
    for (int j = 0; j < 8; j++)
#pragma unroll
        for (int k = 0; k < 4; k++) acc[j][k] = 0.0f;

    pdl_wait();      // attn(t) fully done -> wx valid

    load_tileA(par, sb + SM_TILES, 0, b0, tid);             // G2
    asm volatile("cp.async.commit_group;" ::: "memory");
    load_tileA(par, sb + SM_TILES + TILE_BYTES, 1, b0, tid);// G3
    asm volatile("cp.async.commit_group;" ::: "memory");

    for (int kt = 0; kt < 12; kt++) {
        if (kt < 10) {
            uint32_t sbuf = sb + SM_TILES + ((kt + 2) % 3) * TILE_BYTES;
            load_tileA(par, sbuf, kt + 2, b0, tid);
            load_tileB(sbuf, kt + 2, hu0, tid);
            asm volatile("cp.async.commit_group;" ::: "memory");
            asm volatile("cp.async.wait_group 2;" ::: "memory");
        } else if (kt == 10) {
            asm volatile("cp.async.wait_group 1;" ::: "memory");
        } else {
            asm volatile("cp.async.wait_group 0;" ::: "memory");
        }
        __syncthreads();
        uint32_t base = sb + SM_TILES + (kt % 3) * TILE_BYTES;

#pragma unroll
        for (int ks = 0; ks < 4; ks++) {
            int k0 = ks * 16;
            uint32_t aH[4], aL[4];
            uint32_t bH[16], bL[16];
            uint32_t ar = base + TA_H +
                (w * 16 + (lane & 15)) * LDA + (k0 + (lane >> 4) * 8) * 2;
            LDSM4(aH, ar);
            LDSM4(aL, ar + (TA_L - TA_H));
            int g4 = lane >> 3;
#pragma unroll
            for (int p = 0; p < 4; p++) {
                uint32_t br = base + TB_H +
                    (p * 16 + (g4 >> 1) * 8 + (lane & 7)) * LDA +
                    (k0 + (g4 & 1) * 8) * 2;
                LDSM4(bH + p * 4, br);
                LDSM4(bL + p * 4, br + (TB_L - TB_H));
            }
#pragma unroll
            for (int st = 0; st < 8; st++) MMA16816(acc[st], aH, bH + st * 2);
#pragma unroll
            for (int st = 0; st < 8; st++) MMA16816(acc[st], aH, bL + st * 2);
#pragma unroll
            for (int st = 0; st < 8; st++) MMA16816(acc[st], aL, bH + st * 2);
        }
        __syncthreads();
    }

    // phase 1: LSTM epilogue; stash h,c in smem (reuses tile area) for t1 partials
    float* hcs = (float*)(smem + SM_TILES);   // [64][32]: u<16 = h, u+16 = c
    int qr = lane >> 2, qc = (lane & 3) * 2;
    int wpar = (t + 1) & 1;
    __nv_bfloat16* Ahn = g_Ah[wpar];
    __nv_bfloat16* Aln = g_Al[wpar];
#pragma unroll
    for (int rr = 0; rr < 2; rr++) {
        int bl = w * 16 + rr * 8 + qr;
        int b = b0 + bl;
#pragma unroll
        for (int ug = 0; ug < 2; ug++) {
#pragma unroll
            for (int cc = 0; cc < 2; cc++) {
                int u = ug * 8 + qc + cc;
                int ri = rr * 2 + cc;
                float gi = acc[ug][ri]     + bsum[u];
                float gf = acc[2 + ug][ri] + bsum[16 + u];
                float gg = acc[4 + ug][ri] + bsum[32 + u];
                float go = acc[6 + ug][ri] + bsum[48 + u];
                float I = fsig(gi), F = fsig(gf), G = ftanh(gg), O = fsig(go);
                int hu = hu0 + u;
                int idx = b * HH + hu;
                float c = F * g_c[idx] + I * G;
                float h = O * ftanh(c);
                g_c[idx] = c;
                hcs[bl * 32 + u] = h;
                hcs[bl * 32 + 16 + u] = c;
                out[OFF_IE + (size_t)(b * TM1 + t) * HH + hu] = h;
                __nv_bfloat16 hb = __float2bfloat16(h);
                Ahn[(size_t)b * KTOT + NI + hu] = hb;
                Aln[(size_t)b * KTOT + NI + hu] =
                    __float2bfloat16(h - __bfloat162float(hb));
            }
        }
    }
    __syncthreads();

    // phase 2: t1 partial for step t+1: p[b][ghu][s] = sum_u h*Wc_h + c*Wc_c
    if (tid < 126) {
        int s = tid >> 1, bh = tid & 1;
        float wv[32];
#pragma unroll
        for (int k = 0; k < 32; k++) wv[k] = swct[k * 65 + s];
#pragma unroll 4
        for (int i = 0; i < 32; i++) {
            int bl = bh * 32 + i;
            const float4* hp = reinterpret_cast<const float4*>(hcs + bl * 32);
            float v = 0.0f;
#pragma unroll
            for (int j = 0; j < 8; j++) {
                float4 q = hp[j];
                v += q.x * wv[4 * j] + q.y * wv[4 * j + 1] +
                     q.z * wv[4 * j + 2] + q.w * wv[4 * j + 3];
            }
            g_t1p[(size_t)(b0 + bl) * 1024 + ghu * 64 + s] = v;
        }
    }
}

// ---------------------------------------------------------------- launch
extern "C" void kernel_launch(void* const* d_in, const int* in_sizes, int n_in,
                              void* d_out, int out_size) {
    const float* x   = (const float*)d_in[0];
    const float* Wih = (const float*)d_in[1];
    const float* Whh = (const float*)d_in[2];
    const float* bih = (const float*)d_in[3];
    const float* bhh = (const float*)d_in[4];
    const float* Wc  = (const float*)d_in[5];
    const float* bc  = (const float*)d_in[6];
    const float* Wd  = (const float*)d_in[7];
    const float* bd  = (const float*)d_in[8];
    const float* Wa  = (const float*)d_in[9];
    const float* ba  = (const float*)d_in[10];
    float* out = (float*)d_out;

    cudaFuncSetAttribute(cell_kernel, cudaFuncAttributeMaxDynamicSharedMemorySize, CELL_SMEM);

    zero_kernel<<<(2 * BB * KTOT + 255) / 256, 256>>>();
    convw_kernel<<<(H4 * KTOT + 255) / 256, 256>>>(Wih, Whh);
    transWc_kernel<<<(512 * 64 + 255) / 256, 256>>>(Wc);
    t2_kernel<<<dim3(BB, 4, 2), 128>>>(x, Wd, bd);

    cudaLaunchAttribute pdlAttr[1];
    pdlAttr[0].id = cudaLaunchAttributeProgrammaticStreamSerialization;
    pdlAttr[0].val.programmaticStreamSerializationAllowed = 1;

    for (int t = 0; t < TM1; t++) {
        // attn(0) launches plainly (its predecessor t2_kernel writes t2h,
        // which attn prefetches PRE-sync). All others use PDL overlap.
        if (t == 0) {
            attn_kernel<<<512, 256>>>(x, Wa, ba, bc, out, t);
        } else {
            cudaLaunchConfig_t cfg = {};
            cfg.gridDim = dim3(512);
            cfg.blockDim = dim3(256);
            cfg.stream = 0;
            cfg.attrs = pdlAttr;
            cfg.numAttrs = 1;
            cudaLaunchKernelEx(&cfg, attn_kernel, x, Wa, ba, bc, out, t);
        }
        {
            cudaLaunchConfig_t cfg = {};
            cfg.gridDim = dim3(128);
            cfg.blockDim = dim3(128);
            cfg.dynamicSmemBytes = CELL_SMEM;
            cfg.stream = 0;
            cfg.attrs = pdlAttr;
            cfg.numAttrs = 1;
            cudaLaunchKernelEx(&cfg, cell_kernel, bih, bhh, out, t);
        }
    }
}